// round 4
// baseline (speedup 1.0000x reference)
#include <cuda_runtime.h>
#include <cuda_bf16.h>
#include <cstdint>
#include <cstdio>

// Problem-size maxima (from reference setup_inputs: N=50000, E=800000, D=128, H=4)
#define NMAX   50000
#define EMAX   800000
#define TOTMAX (EMAX + NMAX)   // edges + self loops

// ---------------- scratch (device globals; no allocation allowed) ----------------
__device__ __align__(16) float g_h1pre[(size_t)NMAX * 512];   // x @ W1      [N,4,128]
__device__ __align__(16) float g_h1   [(size_t)NMAX * 512];   // relu(agg1+b1)
__device__ __align__(16) float g_h2pre[(size_t)NMAX * 128];   // h1 @ W2     [N,1,128]
__device__ __align__(16) float g_es   [NMAX * 4];
__device__ __align__(16) float g_ed   [NMAX * 4];
__device__ __align__(16) float g_m    [NMAX * 4];
__device__ __align__(16) float g_zinv [NMAX * 4];
__device__ __align__(16) float g_ebuf [(size_t)TOTMAX * 4];   // per-edge logits
__device__ int   g_cnt  [NMAX];
__device__ int   g_off  [NMAX + 1];
__device__ int   g_cur  [NMAX];
__device__ int   g_srcs [TOTMAX];               // CSR: src node per edge slot

// ---------------- CSR construction ----------------
__global__ void k_init_cnt(int n) {
    int i = blockIdx.x * blockDim.x + threadIdx.x;
    if (i < n) g_cnt[i] = 1;   // 1 = the self loop
}

__global__ void k_hist(const int* __restrict__ dst, int E) {
    int i = blockIdx.x * blockDim.x + threadIdx.x;
    if (i < E) atomicAdd(&g_cnt[dst[i]], 1);
}

// single-block exclusive scan over g_cnt -> g_off, g_cur
__global__ void k_scan(int n) {
    __shared__ int sh[1024];
    __shared__ int carry;
    int t = threadIdx.x;
    if (t == 0) carry = 0;
    __syncthreads();
    for (int base = 0; base < n; base += 1024) {
        int i = base + t;
        int v = (i < n) ? g_cnt[i] : 0;
        sh[t] = v;
        __syncthreads();
        #pragma unroll
        for (int s = 1; s < 1024; s <<= 1) {
            int add = (t >= s) ? sh[t - s] : 0;
            __syncthreads();
            sh[t] += add;
            __syncthreads();
        }
        int excl = sh[t] - v + carry;
        if (i < n) { g_off[i] = excl; g_cur[i] = excl; }
        __syncthreads();
        if (t == 1023) carry += sh[1023];
        __syncthreads();
    }
    if (t == 0) g_off[n] = carry;
}

__global__ void k_scatter(const int* __restrict__ src,
                          const int* __restrict__ dst, int E, int n) {
    int i = blockIdx.x * blockDim.x + threadIdx.x;
    if (i < E) {
        int d = dst[i];
        int p = atomicAdd(&g_cur[d], 1);
        g_srcs[p] = src[i];
    } else if (i < E + n) {
        int node = i - E;
        int p = atomicAdd(&g_cur[node], 1);
        g_srcs[p] = node;
    }
}

// ---------------- SGEMM: C[M,Nn] = A[M,K] @ B[K,Nn], row-major ----------------
template <int BM, int BN, int BK, int TM, int TN>
__global__ __launch_bounds__((BM / TM) * (BN / TN))
void sgemm_kernel(int M, int Nn, int K,
                  const float* __restrict__ A, const float* __restrict__ B,
                  float* __restrict__ C) {
    __shared__ float As[BK][BM];
    __shared__ float Bs[BK][BN];
    const int tid   = threadIdx.x;
    const int aRow  = tid / (BK / 4);
    const int aCol  = (tid % (BK / 4)) * 4;
    const int bRow  = tid / (BN / 4);
    const int bCol  = (tid % (BN / 4)) * 4;
    const int tRow  = (tid / (BN / TN)) * TM;
    const int tCol  = (tid % (BN / TN)) * TN;
    const int mBase = blockIdx.y * BM;
    const int nBase = blockIdx.x * BN;

    float acc[TM][TN] = {};
    float regM[TM], regN[TN];

    for (int k0 = 0; k0 < K; k0 += BK) {
        int gr = mBase + aRow;
        float4 av = (gr < M) ? *(const float4*)(A + (size_t)gr * K + k0 + aCol)
                             : make_float4(0.f, 0.f, 0.f, 0.f);
        As[aCol + 0][aRow] = av.x;
        As[aCol + 1][aRow] = av.y;
        As[aCol + 2][aRow] = av.z;
        As[aCol + 3][aRow] = av.w;
        *(float4*)&Bs[bRow][bCol] =
            *(const float4*)(B + (size_t)(k0 + bRow) * Nn + nBase + bCol);
        __syncthreads();
        #pragma unroll
        for (int k = 0; k < BK; k++) {
            #pragma unroll
            for (int i = 0; i < TM; i++) regM[i] = As[k][tRow + i];
            #pragma unroll
            for (int j = 0; j < TN; j++) regN[j] = Bs[k][tCol + j];
            #pragma unroll
            for (int i = 0; i < TM; i++)
                #pragma unroll
                for (int j = 0; j < TN; j++)
                    acc[i][j] += regM[i] * regN[j];
        }
        __syncthreads();
    }
    #pragma unroll
    for (int i = 0; i < TM; i++) {
        int gr = mBase + tRow + i;
        if (gr < M) {
            float4* cp = (float4*)(C + (size_t)gr * Nn + nBase + tCol);
            cp[0] = make_float4(acc[i][0], acc[i][1], acc[i][2], acc[i][3]);
            cp[1] = make_float4(acc[i][4], acc[i][5], acc[i][6], acc[i][7]);
        }
    }
}

// ---------------- attention scores: es/ed[n,h] = dot(hpre[n,h,:], a[h,:]) ----------------
template <int H>
__global__ void k_scores(const float* __restrict__ hpre,
                         const float* __restrict__ a_src,
                         const float* __restrict__ a_dst, int n) {
    int gt   = blockIdx.x * blockDim.x + threadIdx.x;
    int wid  = gt >> 5;
    int lane = gt & 31;
    if (wid >= n * H) return;
    int node = wid / H, h = wid % H;
    float4 v = ((const float4*)hpre)[(size_t)(node * H + h) * 32 + lane];
    float4 a = ((const float4*)a_src)[h * 32 + lane];
    float4 b = ((const float4*)a_dst)[h * 32 + lane];
    float s = v.x * a.x + v.y * a.y + v.z * a.z + v.w * a.w;
    float d = v.x * b.x + v.y * b.y + v.z * b.z + v.w * b.w;
    #pragma unroll
    for (int o = 16; o; o >>= 1) {
        s += __shfl_down_sync(0xffffffffu, s, o);
        d += __shfl_down_sync(0xffffffffu, d, o);
    }
    if (lane == 0) { g_es[node * H + h] = s; g_ed[node * H + h] = d; }
}

// ---------------- pass A: per-node online softmax (warp per node) ----------------
template <int H>
__global__ void k_passA(int n) {
    int gt   = blockIdx.x * blockDim.x + threadIdx.x;
    int wid  = gt >> 5;
    int lane = gt & 31;
    if (wid >= n) return;
    int node = wid;
    int s0 = g_off[node], s1 = g_off[node + 1];
    float edv[H], m[H], z[H];
    #pragma unroll
    for (int h = 0; h < H; h++) {
        edv[h] = g_ed[node * H + h];
        m[h]   = -1e30f;
        z[h]   = 0.f;
    }
    for (int j = s0 + lane; j < s1; j += 32) {
        int s = g_srcs[j];
        #pragma unroll
        for (int h = 0; h < H; h++) {
            float e = g_es[s * H + h] + edv[h];
            e = (e > 0.f) ? e : 0.2f * e;            // leaky_relu 0.2
            g_ebuf[(size_t)j * H + h] = e;
            float mn = fmaxf(m[h], e);
            z[h] = z[h] * __expf(m[h] - mn) + __expf(e - mn);
            m[h] = mn;
        }
    }
    #pragma unroll
    for (int o = 16; o; o >>= 1) {
        #pragma unroll
        for (int h = 0; h < H; h++) {
            float mo = __shfl_down_sync(0xffffffffu, m[h], o);
            float zo = __shfl_down_sync(0xffffffffu, z[h], o);
            float mn = fmaxf(m[h], mo);
            z[h] = z[h] * __expf(m[h] - mn) + zo * __expf(mo - mn);
            m[h] = mn;
        }
    }
    if (lane == 0) {
        #pragma unroll
        for (int h = 0; h < H; h++) {
            g_m[node * H + h]    = m[h];
            g_zinv[node * H + h] = 1.0f / z[h];
        }
    }
}

// ---------------- pass B, layer 1: aggregate + bias + relu (warp per node-head) ----------------
__global__ void k_passB1(const float* __restrict__ b1, int n) {
    int gt   = blockIdx.x * blockDim.x + threadIdx.x;
    int wid  = gt >> 5;
    int lane = gt & 31;
    if (wid >= n * 4) return;
    int node = wid >> 2, h = wid & 3;
    int s0 = g_off[node], s1 = g_off[node + 1];
    float m  = g_m[node * 4 + h];
    float zi = g_zinv[node * 4 + h];
    const float4* hp4 = (const float4*)g_h1pre;
    float4 acc = make_float4(0.f, 0.f, 0.f, 0.f);
    for (int j = s0; j < s1; j++) {
        float alpha = __expf(g_ebuf[(size_t)j * 4 + h] - m) * zi;
        int s = g_srcs[j];
        float4 v = hp4[(size_t)(s * 4 + h) * 32 + lane];
        acc.x += alpha * v.x;
        acc.y += alpha * v.y;
        acc.z += alpha * v.z;
        acc.w += alpha * v.w;
    }
    float4 bv = ((const float4*)b1)[h * 32 + lane];
    float4 o;
    o.x = fmaxf(acc.x + bv.x, 0.f);
    o.y = fmaxf(acc.y + bv.y, 0.f);
    o.z = fmaxf(acc.z + bv.z, 0.f);
    o.w = fmaxf(acc.w + bv.w, 0.f);
    ((float4*)g_h1)[(size_t)(node * 4 + h) * 32 + lane] = o;
}

// ---------------- pass B, layer 2: aggregate + bias + FC dot (warp per node) ----------------
__global__ void k_passB2(const float* __restrict__ b2, const float* __restrict__ fcw,
                         const float* __restrict__ fcb, float* __restrict__ out, int n) {
    int gt   = blockIdx.x * blockDim.x + threadIdx.x;
    int wid  = gt >> 5;
    int lane = gt & 31;
    if (wid >= n) return;
    int node = wid;
    int s0 = g_off[node], s1 = g_off[node + 1];
    float m  = g_m[node];
    float zi = g_zinv[node];
    const float4* hp4 = (const float4*)g_h2pre;
    float4 acc = make_float4(0.f, 0.f, 0.f, 0.f);
    for (int j = s0; j < s1; j++) {
        float alpha = __expf(g_ebuf[j] - m) * zi;
        int s = g_srcs[j];
        float4 v = hp4[(size_t)s * 32 + lane];
        acc.x += alpha * v.x;
        acc.y += alpha * v.y;
        acc.z += alpha * v.z;
        acc.w += alpha * v.w;
    }
    float4 bv = ((const float4*)b2)[lane];
    float4 wv = ((const float4*)fcw)[lane];
    float s = (acc.x + bv.x) * wv.x + (acc.y + bv.y) * wv.y +
              (acc.z + bv.z) * wv.z + (acc.w + bv.w) * wv.w;
    #pragma unroll
    for (int o = 16; o; o >>= 1) s += __shfl_down_sync(0xffffffffu, s, o);
    if (lane == 0) out[node] = s + fcb[0];
}

// ---------------- launch ----------------
extern "C" void kernel_launch(void* const* d_in, const int* in_sizes, int n_in,
                              void* d_out, int out_size) {
    const float* x   = (const float*)d_in[0];
    const int*   ei  = (const int*)d_in[1];      // int32 (JAX x64 disabled coerces int64->int32)
    const float* W1  = (const float*)d_in[2];
    const float* a1s = (const float*)d_in[3];
    const float* a1d = (const float*)d_in[4];
    const float* b1  = (const float*)d_in[5];
    const float* W2  = (const float*)d_in[6];
    const float* a2s = (const float*)d_in[7];
    const float* a2d = (const float*)d_in[8];
    const float* b2  = (const float*)d_in[9];
    const float* fcw = (const float*)d_in[10];
    const float* fcb = (const float*)d_in[11];
    float*       out = (float*)d_out;

    const int N = in_sizes[0] / 128;
    const int E = in_sizes[1] / 2;

    float *h1pre, *h1, *h2pre;
    cudaGetSymbolAddress((void**)&h1pre, g_h1pre);
    cudaGetSymbolAddress((void**)&h1,    g_h1);
    cudaGetSymbolAddress((void**)&h2pre, g_h2pre);

    const int* e_src = ei;
    const int* e_dst = ei + E;

    // CSR by destination (self loops included via cnt init = 1)
    k_init_cnt<<<(N + 255) / 256, 256>>>(N);
    k_hist<<<(E + 255) / 256, 256>>>(e_dst, E);
    k_scan<<<1, 1024>>>(N);
    k_scatter<<<(E + N + 255) / 256, 256>>>(e_src, e_dst, E, N);

    // ---- layer 1 (H=4, C=128) ----
    {
        dim3 grid(512 / 128, (N + 127) / 128);
        sgemm_kernel<128, 128, 8, 8, 8><<<grid, 256>>>(N, 512, 128, x, W1, h1pre);
    }
    k_scores<4><<<(N * 4 * 32 + 255) / 256, 256>>>(h1pre, a1s, a1d, N);
    k_passA<4><<<(N * 32 + 255) / 256, 256>>>(N);
    k_passB1<<<(N * 4 * 32 + 255) / 256, 256>>>(b1, N);

    // ---- layer 2 (H=1, C=128) ----
    {
        dim3 grid(128 / 128, (N + 127) / 128);
        sgemm_kernel<128, 128, 8, 8, 8><<<grid, 256>>>(N, 128, 512, h1, W2, h2pre);
    }
    k_scores<1><<<(N * 32 + 255) / 256, 256>>>(h2pre, a2s, a2d, N);
    k_passA<1><<<(N * 32 + 255) / 256, 256>>>(N);
    k_passB2<<<(N * 32 + 255) / 256, 256>>>(b2, fcw, fcb, out, N);
}

// round 5
// speedup vs baseline: 1.1456x; 1.1456x over previous
#include <cuda_runtime.h>
#include <cuda_bf16.h>
#include <cstdint>
#include <cstdio>

// Problem sizes (reference setup_inputs: N=50000, E=800000, D=128, H=4)
#define NMAX   50000
#define EMAX   800000
#define TOTMAX (EMAX + NMAX)   // edges + self loops

// ---------------- scratch (device globals; no allocation allowed) ----------------
__device__ __align__(16) float g_agg  [(size_t)NMAX * 512];   // layer1 aggregated x  [N,4,128]
__device__ __align__(16) float g_h1   [(size_t)NMAX * 512];   // relu(agg@W1 + b1)    [N,512]
__device__ __align__(16) float g_h2pre[(size_t)NMAX * 128];   // h1 @ W2              [N,128]
__device__ __align__(16) float g_es   [NMAX * 4];
__device__ __align__(16) float g_ed   [NMAX * 4];
__device__ __align__(16) float g_ebuf [(size_t)TOTMAX * 4];   // per-edge logits -> alphas
__device__ __align__(16) float g_ws   [4 * 128];              // W1_h @ a1_src[h]
__device__ __align__(16) float g_wd   [4 * 128];              // W1_h @ a1_dst[h]
__device__ int   g_cnt  [NMAX];
__device__ int   g_off  [NMAX + 1];
__device__ int   g_cur  [NMAX];
__device__ int   g_srcs [TOTMAX];               // CSR: src node per edge slot

// ---------------- CSR construction ----------------
__global__ void k_init_cnt(int n) {
    int i = blockIdx.x * blockDim.x + threadIdx.x;
    if (i < n) g_cnt[i] = 1;   // 1 = the self loop
}

__global__ void k_hist(const int* __restrict__ dst, int E) {
    int i = blockIdx.x * blockDim.x + threadIdx.x;
    if (i < E) atomicAdd(&g_cnt[dst[i]], 1);
}

// single-block hierarchical exclusive scan: thread-chunk sums -> shfl scan -> write run
__global__ void k_scan(int n) {
    __shared__ int wsum[32];
    __shared__ int s_total;
    const int t    = threadIdx.x;
    const int lane = t & 31;
    const int w    = t >> 5;
    const int per  = (n + blockDim.x - 1) / blockDim.x;
    const int start = t * per;
    const int end   = min(start + per, n);

    int sum = 0;
    for (int i = start; i < end; i++) sum += g_cnt[i];

    // warp inclusive scan
    int inc = sum;
    #pragma unroll
    for (int o = 1; o < 32; o <<= 1) {
        int v = __shfl_up_sync(0xffffffffu, inc, o);
        if (lane >= o) inc += v;
    }
    if (lane == 31) wsum[w] = inc;
    __syncthreads();
    if (w == 0) {
        int v = wsum[lane];
        int winc = v;
        #pragma unroll
        for (int o = 1; o < 32; o <<= 1) {
            int u = __shfl_up_sync(0xffffffffu, winc, o);
            if (lane >= o) winc += u;
        }
        wsum[lane] = winc - v;          // exclusive warp base
        if (lane == 31) s_total = winc;
    }
    __syncthreads();

    int run = (inc - sum) + wsum[w];
    for (int i = start; i < end; i++) {
        int c = g_cnt[i];
        g_off[i] = run;
        g_cur[i] = run;
        run += c;
    }
    if (t == 0) g_off[n] = s_total;
}

__global__ void k_scatter(const int* __restrict__ src,
                          const int* __restrict__ dst, int E, int n) {
    int i = blockIdx.x * blockDim.x + threadIdx.x;
    if (i < E) {
        int d = dst[i];
        int p = atomicAdd(&g_cur[d], 1);
        g_srcs[p] = src[i];
    } else if (i < E + n) {
        int node = i - E;
        int p = atomicAdd(&g_cur[node], 1);
        g_srcs[p] = node;
    }
}

// ---------------- fold attention vectors through W1: ws[h,k] = sum_c W1[k,h*128+c]*a[h,c] ----------------
__global__ void k_prep_ws(const float* __restrict__ W1,
                          const float* __restrict__ a1s,
                          const float* __restrict__ a1d) {
    int t = threadIdx.x;          // 512 threads: h = t>>7, k = t&127
    int h = t >> 7, k = t & 127;
    float s = 0.f, d = 0.f;
    const float* wrow = W1 + (size_t)k * 512 + h * 128;
    const float* as   = a1s + h * 128;
    const float* ad   = a1d + h * 128;
    #pragma unroll 8
    for (int c = 0; c < 128; c++) {
        float wv = wrow[c];
        s += wv * as[c];
        d += wv * ad[c];
    }
    g_ws[t] = s;
    g_wd[t] = d;
}

// ---------------- layer-1 scores from x directly: es[n,h] = x[n]·ws[h] ----------------
__global__ void k_scores1(const float* __restrict__ x, int n) {
    int gt   = blockIdx.x * blockDim.x + threadIdx.x;
    int wid  = gt >> 5;
    int lane = gt & 31;
    if (wid >= n) return;
    float4 v = ((const float4*)x)[(size_t)wid * 32 + lane];
    float s[4], d[4];
    #pragma unroll
    for (int h = 0; h < 4; h++) {
        float4 w = ((const float4*)g_ws)[h * 32 + lane];
        float4 u = ((const float4*)g_wd)[h * 32 + lane];
        s[h] = v.x * w.x + v.y * w.y + v.z * w.z + v.w * w.w;
        d[h] = v.x * u.x + v.y * u.y + v.z * u.z + v.w * u.w;
    }
    #pragma unroll
    for (int o = 16; o; o >>= 1) {
        #pragma unroll
        for (int h = 0; h < 4; h++) {
            s[h] += __shfl_down_sync(0xffffffffu, s[h], o);
            d[h] += __shfl_down_sync(0xffffffffu, d[h], o);
        }
    }
    if (lane == 0) {
        #pragma unroll
        for (int h = 0; h < 4; h++) {
            g_es[wid * 4 + h] = s[h];
            g_ed[wid * 4 + h] = d[h];
        }
    }
}

// ---------------- layer-2 scores: es/ed[n] = dot(h2pre[n,:], a[:]) ----------------
__global__ void k_scores2(const float* __restrict__ hpre,
                          const float* __restrict__ a_src,
                          const float* __restrict__ a_dst, int n) {
    int gt   = blockIdx.x * blockDim.x + threadIdx.x;
    int wid  = gt >> 5;
    int lane = gt & 31;
    if (wid >= n) return;
    float4 v = ((const float4*)hpre)[(size_t)wid * 32 + lane];
    float4 a = ((const float4*)a_src)[lane];
    float4 b = ((const float4*)a_dst)[lane];
    float s = v.x * a.x + v.y * a.y + v.z * a.z + v.w * a.w;
    float d = v.x * b.x + v.y * b.y + v.z * b.z + v.w * b.w;
    #pragma unroll
    for (int o = 16; o; o >>= 1) {
        s += __shfl_down_sync(0xffffffffu, s, o);
        d += __shfl_down_sync(0xffffffffu, d, o);
    }
    if (lane == 0) { g_es[wid] = s; g_ed[wid] = d; }
}

// ---------------- pass A: online softmax per node, then rewrite ebuf as alphas ----------------
template <int H>
__global__ void k_passA(int n) {
    int gt   = blockIdx.x * blockDim.x + threadIdx.x;
    int wid  = gt >> 5;
    int lane = gt & 31;
    if (wid >= n) return;
    const int node = wid;
    const int s0 = g_off[node], s1 = g_off[node + 1];
    float edv[H], m[H], z[H];
    #pragma unroll
    for (int h = 0; h < H; h++) {
        edv[h] = g_ed[node * H + h];
        m[h]   = -1e30f;
        z[h]   = 0.f;
    }
    for (int j = s0 + lane; j < s1; j += 32) {
        int s = g_srcs[j];
        if (H == 4) {
            float4 ev = ((const float4*)g_es)[s];
            float e4[4] = {ev.x, ev.y, ev.z, ev.w};
            float o4[4];
            #pragma unroll
            for (int h = 0; h < 4; h++) {
                float e = e4[h] + edv[h];
                e = (e > 0.f) ? e : 0.2f * e;
                o4[h] = e;
                float mn = fmaxf(m[h], e);
                z[h] = z[h] * __expf(m[h] - mn) + __expf(e - mn);
                m[h] = mn;
            }
            ((float4*)g_ebuf)[j] = make_float4(o4[0], o4[1], o4[2], o4[3]);
        } else {
            float e = g_es[s] + edv[0];
            e = (e > 0.f) ? e : 0.2f * e;
            g_ebuf[j] = e;
            float mn = fmaxf(m[0], e);
            z[0] = z[0] * __expf(m[0] - mn) + __expf(e - mn);
            m[0] = mn;
        }
    }
    // butterfly combine: every lane ends with the final m,z
    #pragma unroll
    for (int o = 16; o; o >>= 1) {
        #pragma unroll
        for (int h = 0; h < H; h++) {
            float mo = __shfl_xor_sync(0xffffffffu, m[h], o);
            float zo = __shfl_xor_sync(0xffffffffu, z[h], o);
            float mn = fmaxf(m[h], mo);
            z[h] = z[h] * __expf(m[h] - mn) + zo * __expf(mo - mn);
            m[h] = mn;
        }
    }
    float zinv[H];
    #pragma unroll
    for (int h = 0; h < H; h++) zinv[h] = 1.0f / z[h];

    // rewrite logits as final alphas (coalesced; per-lane head index is constant)
    {
        int idx0 = s0 * H + lane;
        int hh   = idx0 & (H - 1);
        float mh = m[0], zh = zinv[0];
        #pragma unroll
        for (int h = 1; h < H; h++) {
            if (hh == h) { mh = m[h]; zh = zinv[h]; }
        }
        for (int idx = idx0; idx < s1 * H; idx += 32) {
            float e = g_ebuf[idx];
            g_ebuf[idx] = __expf(e - mh) * zh;
        }
    }
}

// ---------------- layer-1 aggregation of RAW x (warp per node, 4 heads at once) ----------------
__global__ void k_aggX(const float* __restrict__ x, int n) {
    int gt   = blockIdx.x * blockDim.x + threadIdx.x;
    int wid  = gt >> 5;
    int lane = gt & 31;
    if (wid >= n) return;
    const int s0 = g_off[wid], s1 = g_off[wid + 1];
    const float4* x4  = (const float4*)x;
    const float4* al4 = (const float4*)g_ebuf;
    float4 a0 = make_float4(0.f,0.f,0.f,0.f), a1 = a0, a2 = a0, a3 = a0;
    for (int j = s0; j < s1; j++) {
        float4 al = al4[j];                         // uniform across warp (broadcast)
        int s = g_srcs[j];                          // uniform
        float4 v = x4[(size_t)s * 32 + lane];       // 512 B gather, L2-resident (x = 25.6 MB)
        a0.x += al.x * v.x; a0.y += al.x * v.y; a0.z += al.x * v.z; a0.w += al.x * v.w;
        a1.x += al.y * v.x; a1.y += al.y * v.y; a1.z += al.y * v.z; a1.w += al.y * v.w;
        a2.x += al.z * v.x; a2.y += al.z * v.y; a2.z += al.z * v.z; a2.w += al.z * v.w;
        a3.x += al.w * v.x; a3.y += al.w * v.y; a3.z += al.w * v.z; a3.w += al.w * v.w;
    }
    float4* agg4 = (float4*)g_agg;
    size_t base = (size_t)wid * 4;
    agg4[(base + 0) * 32 + lane] = a0;
    agg4[(base + 1) * 32 + lane] = a1;
    agg4[(base + 2) * 32 + lane] = a2;
    agg4[(base + 3) * 32 + lane] = a3;
}

// ---------------- SGEMM (strided, optional z-batched block-diagonal, optional bias+relu) ----------------
template <int BM, int BN, int BK, int TM, int TN, bool EPI>
__global__ __launch_bounds__((BM / TM) * (BN / TN))
void sgemm_kernel(int M, int K,
                  const float* __restrict__ A, int lda,
                  const float* __restrict__ B, int ldb,
                  float* __restrict__ C, int ldc,
                  const float* __restrict__ bias, int offZ) {
    __shared__ float As[BK][BM];
    __shared__ float Bs[BK][BN];
    const int tid   = threadIdx.x;
    const int aRow  = tid / (BK / 4);
    const int aCol  = (tid % (BK / 4)) * 4;
    const int bRow  = tid / (BN / 4);
    const int bCol  = (tid % (BN / 4)) * 4;
    const int tRow  = (tid / (BN / TN)) * TM;
    const int tCol  = (tid % (BN / TN)) * TN;
    const int mBase = blockIdx.y * BM;
    const int nBase = blockIdx.x * BN;
    const int off   = blockIdx.z * offZ;   // block-diagonal head offset

    float acc[TM][TN] = {};
    float regM[TM], regN[TN];

    for (int k0 = 0; k0 < K; k0 += BK) {
        int gr = mBase + aRow;
        float4 av = (gr < M) ? *(const float4*)(A + (size_t)gr * lda + off + k0 + aCol)
                             : make_float4(0.f, 0.f, 0.f, 0.f);
        As[aCol + 0][aRow] = av.x;
        As[aCol + 1][aRow] = av.y;
        As[aCol + 2][aRow] = av.z;
        As[aCol + 3][aRow] = av.w;
        *(float4*)&Bs[bRow][bCol] =
            *(const float4*)(B + (size_t)(k0 + bRow) * ldb + off + nBase + bCol);
        __syncthreads();
        #pragma unroll
        for (int k = 0; k < BK; k++) {
            #pragma unroll
            for (int i = 0; i < TM; i++) regM[i] = As[k][tRow + i];
            #pragma unroll
            for (int j = 0; j < TN; j++) regN[j] = Bs[k][tCol + j];
            #pragma unroll
            for (int i = 0; i < TM; i++)
                #pragma unroll
                for (int j = 0; j < TN; j++)
                    acc[i][j] += regM[i] * regN[j];
        }
        __syncthreads();
    }
    #pragma unroll
    for (int i = 0; i < TM; i++) {
        int gr = mBase + tRow + i;
        if (gr < M) {
            #pragma unroll
            for (int jj = 0; jj < TN; jj += 4) {
                float4 o;
                float* pv = &acc[i][jj];
                if (EPI) {
                    int col = off + nBase + tCol + jj;
                    o.x = fmaxf(pv[0] + bias[col + 0], 0.f);
                    o.y = fmaxf(pv[1] + bias[col + 1], 0.f);
                    o.z = fmaxf(pv[2] + bias[col + 2], 0.f);
                    o.w = fmaxf(pv[3] + bias[col + 3], 0.f);
                } else {
                    o = make_float4(pv[0], pv[1], pv[2], pv[3]);
                }
                *(float4*)(C + (size_t)gr * ldc + off + nBase + tCol + jj) = o;
            }
        }
    }
}

// ---------------- pass B, layer 2: aggregate h2pre + bias + FC dot (warp per node) ----------------
__global__ void k_passB2(const float* __restrict__ b2, const float* __restrict__ fcw,
                         const float* __restrict__ fcb, float* __restrict__ out, int n) {
    int gt   = blockIdx.x * blockDim.x + threadIdx.x;
    int wid  = gt >> 5;
    int lane = gt & 31;
    if (wid >= n) return;
    const int s0 = g_off[wid], s1 = g_off[wid + 1];
    const float4* hp4 = (const float4*)g_h2pre;
    float4 acc = make_float4(0.f, 0.f, 0.f, 0.f);
    for (int j = s0; j < s1; j++) {
        float alpha = g_ebuf[j];                  // already softmaxed
        int s = g_srcs[j];
        float4 v = hp4[(size_t)s * 32 + lane];
        acc.x += alpha * v.x;
        acc.y += alpha * v.y;
        acc.z += alpha * v.z;
        acc.w += alpha * v.w;
    }
    float4 bv = ((const float4*)b2)[lane];
    float4 wv = ((const float4*)fcw)[lane];
    float s = (acc.x + bv.x) * wv.x + (acc.y + bv.y) * wv.y +
              (acc.z + bv.z) * wv.z + (acc.w + bv.w) * wv.w;
    #pragma unroll
    for (int o = 16; o; o >>= 1) s += __shfl_down_sync(0xffffffffu, s, o);
    if (lane == 0) out[wid] = s + fcb[0];
}

// ---------------- launch ----------------
extern "C" void kernel_launch(void* const* d_in, const int* in_sizes, int n_in,
                              void* d_out, int out_size) {
    const float* x   = (const float*)d_in[0];
    const int*   ei  = (const int*)d_in[1];      // int32
    const float* W1  = (const float*)d_in[2];
    const float* a1s = (const float*)d_in[3];
    const float* a1d = (const float*)d_in[4];
    const float* b1  = (const float*)d_in[5];
    const float* W2  = (const float*)d_in[6];
    const float* a2s = (const float*)d_in[7];
    const float* a2d = (const float*)d_in[8];
    const float* b2  = (const float*)d_in[9];
    const float* fcw = (const float*)d_in[10];
    const float* fcb = (const float*)d_in[11];
    float*       out = (float*)d_out;

    const int N = in_sizes[0] / 128;
    const int E = in_sizes[1] / 2;

    float *agg, *h1, *h2pre;
    cudaGetSymbolAddress((void**)&agg,   g_agg);
    cudaGetSymbolAddress((void**)&h1,    g_h1);
    cudaGetSymbolAddress((void**)&h2pre, g_h2pre);

    const int* e_src = ei;
    const int* e_dst = ei + E;

    // CSR by destination (self loops included via cnt init = 1)
    k_init_cnt<<<(N + 255) / 256, 256>>>(N);
    k_hist<<<(E + 255) / 256, 256>>>(e_dst, E);
    k_scan<<<1, 1024>>>(N);
    k_scatter<<<(E + N + 255) / 256, 256>>>(e_src, e_dst, E, N);

    // ---- layer 1 (H=4, C=128): aggregate raw x, then block-diagonal GEMM ----
    k_prep_ws<<<1, 512>>>(W1, a1s, a1d);
    k_scores1<<<(N * 32 + 255) / 256, 256>>>(x, N);
    k_passA<4><<<(N * 32 + 255) / 256, 256>>>(N);
    k_aggX<<<(N * 32 + 255) / 256, 256>>>(x, N);
    {
        dim3 grid(1, (N + 127) / 128, 4);   // z = head
        sgemm_kernel<128, 128, 8, 8, 8, true><<<grid, 256>>>(
            N, 128, agg, 512, W1, 512, h1, 512, b1, 128);
    }

    // ---- layer 2 (H=1, C=128): project then aggregate ----
    {
        dim3 grid(1, (N + 127) / 128, 1);
        sgemm_kernel<128, 128, 8, 8, 8, false><<<grid, 256>>>(
            N, 512, h1, 512, W2, 128, h2pre, 128, nullptr, 0);
    }
    k_scores2<<<(N * 32 + 255) / 256, 256>>>(h2pre, a2s, a2d, N);
    k_passA<1><<<(N * 32 + 255) / 256, 256>>>(N);
    k_passB2<<<(N * 32 + 255) / 256, 256>>>(b2, fcw, fcb, out, N);
}

// round 7
// speedup vs baseline: 1.2784x; 1.1160x over previous
#include <cuda_runtime.h>
#include <cuda_bf16.h>
#include <cstdint>
#include <cstdio>

// Problem sizes (reference setup_inputs: N=50000, E=800000, D=128, H=4)
#define NMAX   50000
#define EMAX   800000
#define TOTMAX (EMAX + NMAX)   // edges + self loops

// ---------------- scratch (device globals; no allocation allowed) ----------------
__device__ __align__(16) float g_agg  [(size_t)NMAX * 512];   // layer1 aggregated x  [N,4,128]
__device__ __align__(16) float g_h1   [(size_t)NMAX * 512];   // relu(agg@W1 + b1)    [N,512]
__device__ __align__(16) float g_h2pre[(size_t)NMAX * 128];   // h1 @ W2              [N,128]
__device__ __align__(16) float g_es   [NMAX * 4];
__device__ __align__(16) float g_ed   [NMAX * 4];
__device__ __align__(16) float g_ebuf [(size_t)TOTMAX * 4];   // per-edge logits -> alphas
__device__ __align__(16) float g_ws   [4 * 128];              // W1_h @ a1_src[h]
__device__ __align__(16) float g_wd   [4 * 128];              // W1_h @ a1_dst[h]
__device__ int   g_cnt  [NMAX];
__device__ int   g_off  [NMAX + 1];
__device__ int   g_cur  [NMAX];
__device__ int   g_srcs [TOTMAX];               // CSR: src node per edge slot

// ---------------- CSR construction ----------------
__global__ void k_init_cnt(int n) {
    int i = blockIdx.x * blockDim.x + threadIdx.x;
    if (i < n) g_cnt[i] = 1;   // 1 = the self loop
}

__global__ void k_hist(const int* __restrict__ dst, int E) {
    int i = blockIdx.x * blockDim.x + threadIdx.x;
    if (i < E) atomicAdd(&g_cnt[dst[i]], 1);
}

// single-block hierarchical exclusive scan
__global__ void k_scan(int n) {
    __shared__ int wsum[32];
    __shared__ int s_total;
    const int t    = threadIdx.x;
    const int lane = t & 31;
    const int w    = t >> 5;
    const int per  = (n + blockDim.x - 1) / blockDim.x;
    const int start = t * per;
    const int end   = min(start + per, n);

    int sum = 0;
    for (int i = start; i < end; i++) sum += g_cnt[i];

    int inc = sum;
    #pragma unroll
    for (int o = 1; o < 32; o <<= 1) {
        int v = __shfl_up_sync(0xffffffffu, inc, o);
        if (lane >= o) inc += v;
    }
    if (lane == 31) wsum[w] = inc;
    __syncthreads();
    if (w == 0) {
        int v = wsum[lane];
        int winc = v;
        #pragma unroll
        for (int o = 1; o < 32; o <<= 1) {
            int u = __shfl_up_sync(0xffffffffu, winc, o);
            if (lane >= o) winc += u;
        }
        wsum[lane] = winc - v;
        if (lane == 31) s_total = winc;
    }
    __syncthreads();

    int run = (inc - sum) + wsum[w];
    for (int i = start; i < end; i++) {
        int c = g_cnt[i];
        g_off[i] = run;
        g_cur[i] = run;
        run += c;
    }
    if (t == 0) g_off[n] = s_total;
}

__global__ void k_scatter(const int* __restrict__ src,
                          const int* __restrict__ dst, int E, int n) {
    int i = blockIdx.x * blockDim.x + threadIdx.x;
    if (i < E) {
        int d = dst[i];
        int p = atomicAdd(&g_cur[d], 1);
        g_srcs[p] = src[i];
    } else if (i < E + n) {
        int node = i - E;
        int p = atomicAdd(&g_cur[node], 1);
        g_srcs[p] = node;
    }
}

// ---------------- fold attention vectors through W1 ----------------
__global__ void k_prep_ws(const float* __restrict__ W1,
                          const float* __restrict__ a1s,
                          const float* __restrict__ a1d) {
    int t = threadIdx.x;          // 512 threads: h = t>>7, k = t&127
    int h = t >> 7, k = t & 127;
    float s = 0.f, d = 0.f;
    const float* wrow = W1 + (size_t)k * 512 + h * 128;
    const float* as   = a1s + h * 128;
    const float* ad   = a1d + h * 128;
    #pragma unroll 8
    for (int c = 0; c < 128; c++) {
        float wv = wrow[c];
        s += wv * as[c];
        d += wv * ad[c];
    }
    g_ws[t] = s;
    g_wd[t] = d;
}

// ---------------- layer-1 scores from x directly ----------------
__global__ void k_scores1(const float* __restrict__ x, int n) {
    int gt   = blockIdx.x * blockDim.x + threadIdx.x;
    int wid  = gt >> 5;
    int lane = gt & 31;
    if (wid >= n) return;
    float4 v = ((const float4*)x)[(size_t)wid * 32 + lane];
    float s[4], d[4];
    #pragma unroll
    for (int h = 0; h < 4; h++) {
        float4 w = ((const float4*)g_ws)[h * 32 + lane];
        float4 u = ((const float4*)g_wd)[h * 32 + lane];
        s[h] = v.x * w.x + v.y * w.y + v.z * w.z + v.w * w.w;
        d[h] = v.x * u.x + v.y * u.y + v.z * u.z + v.w * u.w;
    }
    #pragma unroll
    for (int o = 16; o; o >>= 1) {
        #pragma unroll
        for (int h = 0; h < 4; h++) {
            s[h] += __shfl_down_sync(0xffffffffu, s[h], o);
            d[h] += __shfl_down_sync(0xffffffffu, d[h], o);
        }
    }
    if (lane == 0) {
        #pragma unroll
        for (int h = 0; h < 4; h++) {
            g_es[wid * 4 + h] = s[h];
            g_ed[wid * 4 + h] = d[h];
        }
    }
}

// ---------------- layer-2 scores ----------------
__global__ void k_scores2(const float* __restrict__ hpre,
                          const float* __restrict__ a_src,
                          const float* __restrict__ a_dst, int n) {
    int gt   = blockIdx.x * blockDim.x + threadIdx.x;
    int wid  = gt >> 5;
    int lane = gt & 31;
    if (wid >= n) return;
    float4 v = ((const float4*)hpre)[(size_t)wid * 32 + lane];
    float4 a = ((const float4*)a_src)[lane];
    float4 b = ((const float4*)a_dst)[lane];
    float s = v.x * a.x + v.y * a.y + v.z * a.z + v.w * a.w;
    float d = v.x * b.x + v.y * b.y + v.z * b.z + v.w * b.w;
    #pragma unroll
    for (int o = 16; o; o >>= 1) {
        s += __shfl_down_sync(0xffffffffu, s, o);
        d += __shfl_down_sync(0xffffffffu, d, o);
    }
    if (lane == 0) { g_es[wid] = s; g_ed[wid] = d; }
}

// ---------------- pass A: online softmax per node, rewrite ebuf as alphas ----------------
template <int H>
__global__ void k_passA(int n) {
    int gt   = blockIdx.x * blockDim.x + threadIdx.x;
    int wid  = gt >> 5;
    int lane = gt & 31;
    if (wid >= n) return;
    const int node = wid;
    const int s0 = g_off[node], s1 = g_off[node + 1];
    float edv[H], m[H], z[H];
    #pragma unroll
    for (int h = 0; h < H; h++) {
        edv[h] = g_ed[node * H + h];
        m[h]   = -1e30f;
        z[h]   = 0.f;
    }
    for (int j = s0 + lane; j < s1; j += 32) {
        int s = g_srcs[j];
        if (H == 4) {
            float4 ev = ((const float4*)g_es)[s];
            float e4[4] = {ev.x, ev.y, ev.z, ev.w};
            float o4[4];
            #pragma unroll
            for (int h = 0; h < 4; h++) {
                float e = e4[h] + edv[h];
                e = (e > 0.f) ? e : 0.2f * e;
                o4[h] = e;
                float mn = fmaxf(m[h], e);
                z[h] = z[h] * __expf(m[h] - mn) + __expf(e - mn);
                m[h] = mn;
            }
            ((float4*)g_ebuf)[j] = make_float4(o4[0], o4[1], o4[2], o4[3]);
        } else {
            float e = g_es[s] + edv[0];
            e = (e > 0.f) ? e : 0.2f * e;
            g_ebuf[j] = e;
            float mn = fmaxf(m[0], e);
            z[0] = z[0] * __expf(m[0] - mn) + __expf(e - mn);
            m[0] = mn;
        }
    }
    #pragma unroll
    for (int o = 16; o; o >>= 1) {
        #pragma unroll
        for (int h = 0; h < H; h++) {
            float mo = __shfl_xor_sync(0xffffffffu, m[h], o);
            float zo = __shfl_xor_sync(0xffffffffu, z[h], o);
            float mn = fmaxf(m[h], mo);
            z[h] = z[h] * __expf(m[h] - mn) + zo * __expf(mo - mn);
            m[h] = mn;
        }
    }
    float zinv[H];
    #pragma unroll
    for (int h = 0; h < H; h++) zinv[h] = 1.0f / z[h];

    {
        int idx0 = s0 * H + lane;
        int hh   = idx0 & (H - 1);
        float mh = m[0], zh = zinv[0];
        #pragma unroll
        for (int h = 1; h < H; h++) {
            if (hh == h) { mh = m[h]; zh = zinv[h]; }
        }
        for (int idx = idx0; idx < s1 * H; idx += 32) {
            float e = g_ebuf[idx];
            g_ebuf[idx] = __expf(e - mh) * zh;
        }
    }
}

// ---------------- layer-1 aggregation of RAW x (warp per node, 4 heads at once) ----------------
__global__ void k_aggX(const float* __restrict__ x, int n) {
    int gt   = blockIdx.x * blockDim.x + threadIdx.x;
    int wid  = gt >> 5;
    int lane = gt & 31;
    if (wid >= n) return;
    const int s0 = g_off[wid], s1 = g_off[wid + 1];
    const float4* x4  = (const float4*)x;
    const float4* al4 = (const float4*)g_ebuf;
    float4 a0 = make_float4(0.f,0.f,0.f,0.f), a1 = a0, a2 = a0, a3 = a0;
    for (int j = s0; j < s1; j++) {
        float4 al = al4[j];
        int s = g_srcs[j];
        float4 v = x4[(size_t)s * 32 + lane];
        a0.x += al.x * v.x; a0.y += al.x * v.y; a0.z += al.x * v.z; a0.w += al.x * v.w;
        a1.x += al.y * v.x; a1.y += al.y * v.y; a1.z += al.y * v.z; a1.w += al.y * v.w;
        a2.x += al.z * v.x; a2.y += al.z * v.y; a2.z += al.z * v.z; a2.w += al.z * v.w;
        a3.x += al.w * v.x; a3.y += al.w * v.y; a3.z += al.w * v.z; a3.w += al.w * v.w;
    }
    float4* agg4 = (float4*)g_agg;
    size_t base = (size_t)wid * 4;
    agg4[(base + 0) * 32 + lane] = a0;
    agg4[(base + 1) * 32 + lane] = a1;
    agg4[(base + 2) * 32 + lane] = a2;
    agg4[(base + 3) * 32 + lane] = a3;
}

// ---------------- 3xTF32 tensor-core GEMM ----------------
// C[M,128] = A[M,K] @ B[K,128] per z-slice (block-diagonal via offA/offB/offC).
// Split each operand x = hi + lo (tf32), compute hi*hi + lo*hi + hi*lo in fp32 accum.
__device__ __forceinline__ float tf32r(float x) {
    uint32_t u;
    asm("cvt.rna.tf32.f32 %0, %1;" : "=r"(u) : "f"(x));
    return __uint_as_float(u);
}

#define MMA_TF32(d, a, b)                                                     \
    asm volatile("mma.sync.aligned.m16n8k8.row.col.f32.tf32.tf32.f32 "        \
                 "{%0,%1,%2,%3}, {%4,%5,%6,%7}, {%8,%9}, {%0,%1,%2,%3};"      \
                 : "+f"(d[0]), "+f"(d[1]), "+f"(d[2]), "+f"(d[3])             \
                 : "r"(a[0]), "r"(a[1]), "r"(a[2]), "r"(a[3]),                \
                   "r"(b[0]), "r"(b[1]))

template <bool EPI>
__global__ __launch_bounds__(256)
void mma_gemm(int M, int K,
              const float* __restrict__ A, int lda, int offA,
              const float* __restrict__ B, int ldb, int offB,
              float* __restrict__ C, int ldc, int offC,
              const float* __restrict__ bias) {
    __shared__ float AsH[16][136], AsL[16][136];   // [k][m], padded stride 136
    __shared__ float BsH[16][136], BsL[16][136];   // [k][n]
    const int tid  = threadIdx.x;
    const int lane = tid & 31;
    const int wid  = tid >> 5;
    const int wm   = (wid & 3) * 32;   // 4 warps along m
    const int wn   = (wid >> 2) * 64;  // 2 warps along n
    const int mBase = blockIdx.y * 128;
    const int zA = blockIdx.z * offA;
    const int zB = blockIdx.z * offB;
    const int zC = blockIdx.z * offC;

    const int aRow = tid >> 2;          // 0..63
    const int aK   = (tid & 3) * 4;     // 0,4,8,12
    const int bK   = tid >> 5;          // 0..7
    const int bN   = (tid & 31) * 4;    // 0..124

    float acc[2][8][4];
    #pragma unroll
    for (int i = 0; i < 2; i++)
        #pragma unroll
        for (int j = 0; j < 8; j++)
            #pragma unroll
            for (int q = 0; q < 4; q++) acc[i][j][q] = 0.f;

    for (int k0 = 0; k0 < K; k0 += 16) {
        // load A tile [128 x 16] -> smem [k][m] hi/lo
        #pragma unroll
        for (int rr = 0; rr < 2; rr++) {
            int gr = mBase + aRow + rr * 64;
            float4 v = make_float4(0.f, 0.f, 0.f, 0.f);
            if (gr < M) v = *(const float4*)(A + (size_t)gr * lda + zA + k0 + aK);
            int mm = aRow + rr * 64;
            float h0 = tf32r(v.x), l0 = tf32r(v.x - h0);
            float h1v = tf32r(v.y), l1 = tf32r(v.y - h1v);
            float h2 = tf32r(v.z), l2 = tf32r(v.z - h2);
            float h3 = tf32r(v.w), l3 = tf32r(v.w - h3);
            AsH[aK + 0][mm] = h0; AsL[aK + 0][mm] = l0;
            AsH[aK + 1][mm] = h1v; AsL[aK + 1][mm] = l1;
            AsH[aK + 2][mm] = h2; AsL[aK + 2][mm] = l2;
            AsH[aK + 3][mm] = h3; AsL[aK + 3][mm] = l3;
        }
        // load B tile [16 x 128] -> smem [k][n] hi/lo
        #pragma unroll
        for (int rr = 0; rr < 2; rr++) {
            int gk = k0 + bK + rr * 8;
            float4 v = *(const float4*)(B + (size_t)gk * ldb + zB + bN);
            float4 h, l;
            h.x = tf32r(v.x); l.x = tf32r(v.x - h.x);
            h.y = tf32r(v.y); l.y = tf32r(v.y - h.y);
            h.z = tf32r(v.z); l.z = tf32r(v.z - h.z);
            h.w = tf32r(v.w); l.w = tf32r(v.w - h.w);
            *(float4*)&BsH[bK + rr * 8][bN] = h;
            *(float4*)&BsL[bK + rr * 8][bN] = l;
        }
        __syncthreads();
        #pragma unroll
        for (int kk = 0; kk < 16; kk += 8) {
            uint32_t ah[2][4], al[2][4];
            const int ar = wm + (lane >> 2);
            const int ac = kk + (lane & 3);
            #pragma unroll
            for (int i = 0; i < 2; i++) {
                int r = ar + i * 16;
                ah[i][0] = __float_as_uint(AsH[ac][r]);
                ah[i][1] = __float_as_uint(AsH[ac][r + 8]);
                ah[i][2] = __float_as_uint(AsH[ac + 4][r]);
                ah[i][3] = __float_as_uint(AsH[ac + 4][r + 8]);
                al[i][0] = __float_as_uint(AsL[ac][r]);
                al[i][1] = __float_as_uint(AsL[ac][r + 8]);
                al[i][2] = __float_as_uint(AsL[ac + 4][r]);
                al[i][3] = __float_as_uint(AsL[ac + 4][r + 8]);
            }
            #pragma unroll
            for (int jh = 0; jh < 2; jh++) {
                uint32_t bh[4][2], bl[4][2];
                const int rB = kk + (lane & 3);
                #pragma unroll
                for (int j = 0; j < 4; j++) {
                    int c = wn + jh * 32 + j * 8 + (lane >> 2);
                    bh[j][0] = __float_as_uint(BsH[rB][c]);
                    bh[j][1] = __float_as_uint(BsH[rB + 4][c]);
                    bl[j][0] = __float_as_uint(BsL[rB][c]);
                    bl[j][1] = __float_as_uint(BsL[rB + 4][c]);
                }
                #pragma unroll
                for (int i = 0; i < 2; i++)
                    #pragma unroll
                    for (int j = 0; j < 4; j++) {
                        float* d = acc[i][jh * 4 + j];
                        MMA_TF32(d, ah[i], bh[j]);
                        MMA_TF32(d, al[i], bh[j]);
                        MMA_TF32(d, ah[i], bl[j]);
                    }
            }
        }
        __syncthreads();
    }
    // epilogue
    #pragma unroll
    for (int i = 0; i < 2; i++) {
        int r0 = mBase + wm + i * 16 + (lane >> 2);
        #pragma unroll
        for (int j = 0; j < 8; j++) {
            int c = wn + j * 8 + (lane & 3) * 2;
            #pragma unroll
            for (int half = 0; half < 2; half++) {
                int row = r0 + half * 8;
                if (row < M) {
                    float vx = acc[i][j][half * 2 + 0];
                    float vy = acc[i][j][half * 2 + 1];
                    if (EPI) {
                        vx = fmaxf(vx + bias[zC + c + 0], 0.f);
                        vy = fmaxf(vy + bias[zC + c + 1], 0.f);
                    }
                    *(float2*)(C + (size_t)row * ldc + zC + c) = make_float2(vx, vy);
                }
            }
        }
    }
}

// ---------------- pass B, layer 2 ----------------
__global__ void k_passB2(const float* __restrict__ b2, const float* __restrict__ fcw,
                         const float* __restrict__ fcb, float* __restrict__ out, int n) {
    int gt   = blockIdx.x * blockDim.x + threadIdx.x;
    int wid  = gt >> 5;
    int lane = gt & 31;
    if (wid >= n) return;
    const int s0 = g_off[wid], s1 = g_off[wid + 1];
    const float4* hp4 = (const float4*)g_h2pre;
    float4 acc = make_float4(0.f, 0.f, 0.f, 0.f);
    for (int j = s0; j < s1; j++) {
        float alpha = g_ebuf[j];
        int s = g_srcs[j];
        float4 v = hp4[(size_t)s * 32 + lane];
        acc.x += alpha * v.x;
        acc.y += alpha * v.y;
        acc.z += alpha * v.z;
        acc.w += alpha * v.w;
    }
    float4 bv = ((const float4*)b2)[lane];
    float4 wv = ((const float4*)fcw)[lane];
    float s = (acc.x + bv.x) * wv.x + (acc.y + bv.y) * wv.y +
              (acc.z + bv.z) * wv.z + (acc.w + bv.w) * wv.w;
    #pragma unroll
    for (int o = 16; o; o >>= 1) s += __shfl_down_sync(0xffffffffu, s, o);
    if (lane == 0) out[wid] = s + fcb[0];
}

// ---------------- launch ----------------
extern "C" void kernel_launch(void* const* d_in, const int* in_sizes, int n_in,
                              void* d_out, int out_size) {
    const float* x   = (const float*)d_in[0];
    const int*   ei  = (const int*)d_in[1];      // int32
    const float* W1  = (const float*)d_in[2];
    const float* a1s = (const float*)d_in[3];
    const float* a1d = (const float*)d_in[4];
    const float* b1  = (const float*)d_in[5];
    const float* W2  = (const float*)d_in[6];
    const float* a2s = (const float*)d_in[7];
    const float* a2d = (const float*)d_in[8];
    const float* b2  = (const float*)d_in[9];
    const float* fcw = (const float*)d_in[10];
    const float* fcb = (const float*)d_in[11];
    float*       out = (float*)d_out;

    const int N = in_sizes[0] / 128;
    const int E = in_sizes[1] / 2;

    float *agg, *h1, *h2pre;
    cudaGetSymbolAddress((void**)&agg,   g_agg);
    cudaGetSymbolAddress((void**)&h1,    g_h1);
    cudaGetSymbolAddress((void**)&h2pre, g_h2pre);

    const int* e_src = ei;
    const int* e_dst = ei + E;

    // CSR by destination (self loops included via cnt init = 1)
    k_init_cnt<<<(N + 255) / 256, 256>>>(N);
    k_hist<<<(E + 255) / 256, 256>>>(e_dst, E);
    k_scan<<<1, 1024>>>(N);
    k_scatter<<<(E + N + 255) / 256, 256>>>(e_src, e_dst, E, N);

    // ---- layer 1 (H=4, C=128): aggregate raw x, then block-diagonal 3xTF32 GEMM ----
    k_prep_ws<<<1, 512>>>(W1, a1s, a1d);
    k_scores1<<<(N * 32 + 255) / 256, 256>>>(x, N);
    k_passA<4><<<(N * 32 + 255) / 256, 256>>>(N);
    k_aggX<<<(N * 32 + 255) / 256, 256>>>(x, N);
    {
        dim3 grid(1, (N + 127) / 128, 4);   // z = head
        mma_gemm<true><<<grid, 256>>>(N, 128, agg, 512, 128, W1, 512, 128,
                                      h1, 512, 128, b1);
    }

    // ---- layer 2 (H=1, C=128): project then aggregate ----
    {
        dim3 grid(1, (N + 127) / 128, 1);
        mma_gemm<false><<<grid, 256>>>(N, 512, h1, 512, 0, W2, 128, 0,
                                       h2pre, 128, 0, nullptr);
    }
    k_scores2<<<(N * 32 + 255) / 256, 256>>>(h2pre, a2s, a2d, N);
    k_passA<1><<<(N * 32 + 255) / 256, 256>>>(N);
    k_passB2<<<(N * 32 + 255) / 256, 256>>>(b2, fcw, fcb, out, N);
}

// round 8
// speedup vs baseline: 1.6792x; 1.3135x over previous
#include <cuda_runtime.h>
#include <cuda_bf16.h>
#include <cstdint>
#include <cstdio>

// Problem sizes (reference setup_inputs: N=50000, E=800000, D=128, H=4)
#define NMAX   50000
#define EMAX   800000
#define TOTMAX (EMAX + NMAX)   // edges + self loops

// ---------------- scratch (device globals; no allocation allowed) ----------------
__device__ __align__(16) float g_agg  [(size_t)NMAX * 512];   // layer1 aggregated x  [N,4,128]
__device__ __align__(16) float g_h1   [(size_t)NMAX * 512];   // relu(agg@W1 + b1)    [N,512]
__device__ __align__(16) float g_h2pre[(size_t)NMAX * 128];   // h1 @ W2              [N,128]
__device__ __align__(16) float g_es   [NMAX * 4];
__device__ __align__(16) float g_ed   [NMAX * 4];
__device__ __align__(16) float g_ebuf [(size_t)TOTMAX * 4];   // per-edge logits -> alphas
__device__ __align__(16) float g_ws   [4 * 128];              // W1_h @ a1_src[h]
__device__ __align__(16) float g_wd   [4 * 128];              // W1_h @ a1_dst[h]
__device__ int   g_cnt  [NMAX];
__device__ int   g_off  [NMAX + 1];
__device__ int   g_cur  [NMAX];
__device__ int   g_srcs [TOTMAX];               // CSR: src node per edge slot

// ---------------- CSR construction ----------------
__global__ void k_init_cnt(int n) {
    int i = blockIdx.x * blockDim.x + threadIdx.x;
    if (i < n) g_cnt[i] = 1;   // 1 = the self loop
}

__global__ void k_hist(const int* __restrict__ dst, int E) {
    int i = blockIdx.x * blockDim.x + threadIdx.x;
    if (i < E) atomicAdd(&g_cnt[dst[i]], 1);
}

// single-block hierarchical exclusive scan
__global__ void k_scan(int n) {
    __shared__ int wsum[32];
    __shared__ int s_total;
    const int t    = threadIdx.x;
    const int lane = t & 31;
    const int w    = t >> 5;
    const int per  = (n + blockDim.x - 1) / blockDim.x;
    const int start = t * per;
    const int end   = min(start + per, n);

    int sum = 0;
    for (int i = start; i < end; i++) sum += g_cnt[i];

    int inc = sum;
    #pragma unroll
    for (int o = 1; o < 32; o <<= 1) {
        int v = __shfl_up_sync(0xffffffffu, inc, o);
        if (lane >= o) inc += v;
    }
    if (lane == 31) wsum[w] = inc;
    __syncthreads();
    if (w == 0) {
        int v = wsum[lane];
        int winc = v;
        #pragma unroll
        for (int o = 1; o < 32; o <<= 1) {
            int u = __shfl_up_sync(0xffffffffu, winc, o);
            if (lane >= o) winc += u;
        }
        wsum[lane] = winc - v;
        if (lane == 31) s_total = winc;
    }
    __syncthreads();

    int run = (inc - sum) + wsum[w];
    for (int i = start; i < end; i++) {
        int c = g_cnt[i];
        g_off[i] = run;
        g_cur[i] = run;
        run += c;
    }
    if (t == 0) g_off[n] = s_total;
}

__global__ void k_scatter(const int* __restrict__ src,
                          const int* __restrict__ dst, int E, int n) {
    int i = blockIdx.x * blockDim.x + threadIdx.x;
    if (i < E) {
        int d = dst[i];
        int p = atomicAdd(&g_cur[d], 1);
        g_srcs[p] = src[i];
    } else if (i < E + n) {
        int node = i - E;
        int p = atomicAdd(&g_cur[node], 1);
        g_srcs[p] = node;
    }
}

// ---------------- fold attention vectors through W1 ----------------
__global__ void k_prep_ws(const float* __restrict__ W1,
                          const float* __restrict__ a1s,
                          const float* __restrict__ a1d) {
    int t = threadIdx.x;          // 512 threads: h = t>>7, k = t&127
    int h = t >> 7, k = t & 127;
    float s = 0.f, d = 0.f;
    const float* wrow = W1 + (size_t)k * 512 + h * 128;
    const float* as   = a1s + h * 128;
    const float* ad   = a1d + h * 128;
    #pragma unroll 8
    for (int c = 0; c < 128; c++) {
        float wv = wrow[c];
        s += wv * as[c];
        d += wv * ad[c];
    }
    g_ws[t] = s;
    g_wd[t] = d;
}

// ---------------- layer-1 scores from x directly ----------------
__global__ void k_scores1(const float* __restrict__ x, int n) {
    int gt   = blockIdx.x * blockDim.x + threadIdx.x;
    int wid  = gt >> 5;
    int lane = gt & 31;
    if (wid >= n) return;
    float4 v = ((const float4*)x)[(size_t)wid * 32 + lane];
    float s[4], d[4];
    #pragma unroll
    for (int h = 0; h < 4; h++) {
        float4 w = ((const float4*)g_ws)[h * 32 + lane];
        float4 u = ((const float4*)g_wd)[h * 32 + lane];
        s[h] = v.x * w.x + v.y * w.y + v.z * w.z + v.w * w.w;
        d[h] = v.x * u.x + v.y * u.y + v.z * u.z + v.w * u.w;
    }
    #pragma unroll
    for (int o = 16; o; o >>= 1) {
        #pragma unroll
        for (int h = 0; h < 4; h++) {
            s[h] += __shfl_down_sync(0xffffffffu, s[h], o);
            d[h] += __shfl_down_sync(0xffffffffu, d[h], o);
        }
    }
    if (lane == 0) {
        #pragma unroll
        for (int h = 0; h < 4; h++) {
            g_es[wid * 4 + h] = s[h];
            g_ed[wid * 4 + h] = d[h];
        }
    }
}

// ---------------- layer-2 scores ----------------
__global__ void k_scores2(const float* __restrict__ hpre,
                          const float* __restrict__ a_src,
                          const float* __restrict__ a_dst, int n) {
    int gt   = blockIdx.x * blockDim.x + threadIdx.x;
    int wid  = gt >> 5;
    int lane = gt & 31;
    if (wid >= n) return;
    float4 v = ((const float4*)hpre)[(size_t)wid * 32 + lane];
    float4 a = ((const float4*)a_src)[lane];
    float4 b = ((const float4*)a_dst)[lane];
    float s = v.x * a.x + v.y * a.y + v.z * a.z + v.w * a.w;
    float d = v.x * b.x + v.y * b.y + v.z * b.z + v.w * b.w;
    #pragma unroll
    for (int o = 16; o; o >>= 1) {
        s += __shfl_down_sync(0xffffffffu, s, o);
        d += __shfl_down_sync(0xffffffffu, d, o);
    }
    if (lane == 0) { g_es[wid] = s; g_ed[wid] = d; }
}

// ---------------- pass A: online softmax per node, rewrite ebuf as alphas ----------------
template <int H>
__global__ void k_passA(int n) {
    int gt   = blockIdx.x * blockDim.x + threadIdx.x;
    int wid  = gt >> 5;
    int lane = gt & 31;
    if (wid >= n) return;
    const int node = wid;
    const int s0 = g_off[node], s1 = g_off[node + 1];
    float edv[H], m[H], z[H];
    #pragma unroll
    for (int h = 0; h < H; h++) {
        edv[h] = g_ed[node * H + h];
        m[h]   = -1e30f;
        z[h]   = 0.f;
    }
    for (int j = s0 + lane; j < s1; j += 32) {
        int s = g_srcs[j];
        if (H == 4) {
            float4 ev = ((const float4*)g_es)[s];
            float e4[4] = {ev.x, ev.y, ev.z, ev.w};
            float o4[4];
            #pragma unroll
            for (int h = 0; h < 4; h++) {
                float e = e4[h] + edv[h];
                e = (e > 0.f) ? e : 0.2f * e;
                o4[h] = e;
                float mn = fmaxf(m[h], e);
                z[h] = z[h] * __expf(m[h] - mn) + __expf(e - mn);
                m[h] = mn;
            }
            ((float4*)g_ebuf)[j] = make_float4(o4[0], o4[1], o4[2], o4[3]);
        } else {
            float e = g_es[s] + edv[0];
            e = (e > 0.f) ? e : 0.2f * e;
            g_ebuf[j] = e;
            float mn = fmaxf(m[0], e);
            z[0] = z[0] * __expf(m[0] - mn) + __expf(e - mn);
            m[0] = mn;
        }
    }
    #pragma unroll
    for (int o = 16; o; o >>= 1) {
        #pragma unroll
        for (int h = 0; h < H; h++) {
            float mo = __shfl_xor_sync(0xffffffffu, m[h], o);
            float zo = __shfl_xor_sync(0xffffffffu, z[h], o);
            float mn = fmaxf(m[h], mo);
            z[h] = z[h] * __expf(m[h] - mn) + zo * __expf(mo - mn);
            m[h] = mn;
        }
    }
    float zinv[H];
    #pragma unroll
    for (int h = 0; h < H; h++) zinv[h] = 1.0f / z[h];

    {
        int idx0 = s0 * H + lane;
        int hh   = idx0 & (H - 1);
        float mh = m[0], zh = zinv[0];
        #pragma unroll
        for (int h = 1; h < H; h++) {
            if (hh == h) { mh = m[h]; zh = zinv[h]; }
        }
        for (int idx = idx0; idx < s1 * H; idx += 32) {
            float e = g_ebuf[idx];
            g_ebuf[idx] = __expf(e - mh) * zh;
        }
    }
}

// ---------------- layer-1 aggregation of RAW x (warp per node, 4 heads at once) ----------------
__global__ void k_aggX(const float* __restrict__ x, int n) {
    int gt   = blockIdx.x * blockDim.x + threadIdx.x;
    int wid  = gt >> 5;
    int lane = gt & 31;
    if (wid >= n) return;
    const int s0 = g_off[wid], s1 = g_off[wid + 1];
    const float4* x4  = (const float4*)x;
    const float4* al4 = (const float4*)g_ebuf;
    float4 a0 = make_float4(0.f,0.f,0.f,0.f), a1 = a0, a2 = a0, a3 = a0;
    for (int j = s0; j < s1; j++) {
        float4 al = al4[j];
        int s = g_srcs[j];
        float4 v = x4[(size_t)s * 32 + lane];
        a0.x += al.x * v.x; a0.y += al.x * v.y; a0.z += al.x * v.z; a0.w += al.x * v.w;
        a1.x += al.y * v.x; a1.y += al.y * v.y; a1.z += al.y * v.z; a1.w += al.y * v.w;
        a2.x += al.z * v.x; a2.y += al.z * v.y; a2.z += al.z * v.z; a2.w += al.z * v.w;
        a3.x += al.w * v.x; a3.y += al.w * v.y; a3.z += al.w * v.z; a3.w += al.w * v.w;
    }
    float4* agg4 = (float4*)g_agg;
    size_t base = (size_t)wid * 4;
    agg4[(base + 0) * 32 + lane] = a0;
    agg4[(base + 1) * 32 + lane] = a1;
    agg4[(base + 2) * 32 + lane] = a2;
    agg4[(base + 3) * 32 + lane] = a3;
}

// ---------------- bf16-split tensor-core GEMM ----------------
// C[M,128] = A[M,K] @ B[K,128] per z-slice (block-diagonal via offA/offB/offC).
// Split x = hi + lo (bf16 each); compute hi*hi + lo*hi + hi*lo, fp32 accum.
// Error ~2^-16 relative (missing lo*lo) -- far under 1e-3 gate.
__device__ __forceinline__ uint32_t pack2bf(float a, float b) {
    __nv_bfloat162 t = __floats2bfloat162_rn(a, b);   // .x = a (low half)
    return *reinterpret_cast<uint32_t*>(&t);
}

#define MMA_BF16(d, a, b)                                                     \
    asm volatile("mma.sync.aligned.m16n8k16.row.col.f32.bf16.bf16.f32 "       \
                 "{%0,%1,%2,%3}, {%4,%5,%6,%7}, {%8,%9}, {%0,%1,%2,%3};"      \
                 : "+f"(d[0]), "+f"(d[1]), "+f"(d[2]), "+f"(d[3])             \
                 : "r"(a[0]), "r"(a[1]), "r"(a[2]), "r"(a[3]),                \
                   "r"(b[0]), "r"(b[1]))

template <bool EPI>
__global__ __launch_bounds__(256)
void mma_gemm(int M, int K,
              const float* __restrict__ A, int lda, int offA,
              const float* __restrict__ B, int ldb, int offB,
              float* __restrict__ C, int ldc, int offC,
              const float* __restrict__ bias) {
    // k-packed bf16x2 tiles: [pk][m] / [pk][n], pk = k/2 in 0..7, stride 136 words
    __shared__ uint32_t AsH[8][136], AsL[8][136];
    __shared__ uint32_t BsH[8][136], BsL[8][136];
    const int tid  = threadIdx.x;
    const int lane = tid & 31;
    const int wid  = tid >> 5;
    const int wm   = (wid & 3) * 32;   // 4 warps along m
    const int wn   = (wid >> 2) * 64;  // 2 warps along n
    const int mBase = blockIdx.y * 128;
    const int zA = blockIdx.z * offA;
    const int zB = blockIdx.z * offB;
    const int zC = blockIdx.z * offC;

    const int aRow = tid >> 2;          // 0..63
    const int aK   = (tid & 3) * 4;     // k offset 0,4,8,12
    const int aPk  = (tid & 3) * 2;     // packed col base 0,2,4,6
    const int bPk  = tid >> 5;          // packed k row 0..7
    const int bN   = (tid & 31) * 4;    // 0..124

    float acc[2][8][4];
    #pragma unroll
    for (int i = 0; i < 2; i++)
        #pragma unroll
        for (int j = 0; j < 8; j++)
            #pragma unroll
            for (int q = 0; q < 4; q++) acc[i][j][q] = 0.f;

    for (int k0 = 0; k0 < K; k0 += 16) {
        // ---- A tile [128 x 16] -> packed hi/lo ----
        #pragma unroll
        for (int rr = 0; rr < 2; rr++) {
            int gr = mBase + aRow + rr * 64;
            float4 v = make_float4(0.f, 0.f, 0.f, 0.f);
            if (gr < M) v = *(const float4*)(A + (size_t)gr * lda + zA + k0 + aK);
            int mm = aRow + rr * 64;
            __nv_bfloat16 hx = __float2bfloat16_rn(v.x);
            __nv_bfloat16 hy = __float2bfloat16_rn(v.y);
            __nv_bfloat16 hz = __float2bfloat16_rn(v.z);
            __nv_bfloat16 hw = __float2bfloat16_rn(v.w);
            float lx = v.x - __bfloat162float(hx);
            float ly = v.y - __bfloat162float(hy);
            float lz = v.z - __bfloat162float(hz);
            float lw = v.w - __bfloat162float(hw);
            AsH[aPk + 0][mm] = pack2bf(__bfloat162float(hx), __bfloat162float(hy));
            AsH[aPk + 1][mm] = pack2bf(__bfloat162float(hz), __bfloat162float(hw));
            AsL[aPk + 0][mm] = pack2bf(lx, ly);
            AsL[aPk + 1][mm] = pack2bf(lz, lw);
        }
        // ---- B tile [16 x 128] -> packed hi/lo (pack across two k-rows) ----
        {
            const float* b0p = B + (size_t)(k0 + 2 * bPk) * ldb + zB + bN;
            float4 v0 = *(const float4*)b0p;
            float4 v1 = *(const float4*)(b0p + ldb);
            float e0[4] = {v0.x, v0.y, v0.z, v0.w};
            float e1[4] = {v1.x, v1.y, v1.z, v1.w};
            uint32_t ph[4], pl[4];
            #pragma unroll
            for (int j = 0; j < 4; j++) {
                __nv_bfloat16 h0 = __float2bfloat16_rn(e0[j]);
                __nv_bfloat16 h1 = __float2bfloat16_rn(e1[j]);
                float l0 = e0[j] - __bfloat162float(h0);
                float l1 = e1[j] - __bfloat162float(h1);
                ph[j] = pack2bf(__bfloat162float(h0), __bfloat162float(h1));
                pl[j] = pack2bf(l0, l1);
            }
            *(uint4*)&BsH[bPk][bN] = make_uint4(ph[0], ph[1], ph[2], ph[3]);
            *(uint4*)&BsL[bPk][bN] = make_uint4(pl[0], pl[1], pl[2], pl[3]);
        }
        __syncthreads();

        // ---- one m16n8k16 step consumes the whole 16-wide k tile ----
        uint32_t ah[2][4], al[2][4];
        const int ar = wm + (lane >> 2);
        const int ac = lane & 3;            // packed col 0..3 (k pair), +4 for k+8
        #pragma unroll
        for (int i = 0; i < 2; i++) {
            int r = ar + i * 16;
            ah[i][0] = AsH[ac][r];
            ah[i][1] = AsH[ac][r + 8];
            ah[i][2] = AsH[ac + 4][r];
            ah[i][3] = AsH[ac + 4][r + 8];
            al[i][0] = AsL[ac][r];
            al[i][1] = AsL[ac][r + 8];
            al[i][2] = AsL[ac + 4][r];
            al[i][3] = AsL[ac + 4][r + 8];
        }
        #pragma unroll
        for (int jh = 0; jh < 2; jh++) {
            uint32_t bh[4][2], bl[4][2];
            const int rB = lane & 3;
            #pragma unroll
            for (int j = 0; j < 4; j++) {
                int c = wn + jh * 32 + j * 8 + (lane >> 2);
                bh[j][0] = BsH[rB][c];
                bh[j][1] = BsH[rB + 4][c];
                bl[j][0] = BsL[rB][c];
                bl[j][1] = BsL[rB + 4][c];
            }
            #pragma unroll
            for (int i = 0; i < 2; i++)
                #pragma unroll
                for (int j = 0; j < 4; j++) {
                    float* d = acc[i][jh * 4 + j];
                    MMA_BF16(d, ah[i], bh[j]);
                    MMA_BF16(d, al[i], bh[j]);
                    MMA_BF16(d, ah[i], bl[j]);
                }
        }
        __syncthreads();
    }
    // epilogue (same accumulator layout as m16n8 tf32)
    #pragma unroll
    for (int i = 0; i < 2; i++) {
        int r0 = mBase + wm + i * 16 + (lane >> 2);
        #pragma unroll
        for (int j = 0; j < 8; j++) {
            int c = wn + j * 8 + (lane & 3) * 2;
            #pragma unroll
            for (int half = 0; half < 2; half++) {
                int row = r0 + half * 8;
                if (row < M) {
                    float vx = acc[i][j][half * 2 + 0];
                    float vy = acc[i][j][half * 2 + 1];
                    if (EPI) {
                        vx = fmaxf(vx + bias[zC + c + 0], 0.f);
                        vy = fmaxf(vy + bias[zC + c + 1], 0.f);
                    }
                    *(float2*)(C + (size_t)row * ldc + zC + c) = make_float2(vx, vy);
                }
            }
        }
    }
}

// ---------------- pass B, layer 2 ----------------
__global__ void k_passB2(const float* __restrict__ b2, const float* __restrict__ fcw,
                         const float* __restrict__ fcb, float* __restrict__ out, int n) {
    int gt   = blockIdx.x * blockDim.x + threadIdx.x;
    int wid  = gt >> 5;
    int lane = gt & 31;
    if (wid >= n) return;
    const int s0 = g_off[wid], s1 = g_off[wid + 1];
    const float4* hp4 = (const float4*)g_h2pre;
    float4 acc = make_float4(0.f, 0.f, 0.f, 0.f);
    for (int j = s0; j < s1; j++) {
        float alpha = g_ebuf[j];
        int s = g_srcs[j];
        float4 v = hp4[(size_t)s * 32 + lane];
        acc.x += alpha * v.x;
        acc.y += alpha * v.y;
        acc.z += alpha * v.z;
        acc.w += alpha * v.w;
    }
    float4 bv = ((const float4*)b2)[lane];
    float4 wv = ((const float4*)fcw)[lane];
    float s = (acc.x + bv.x) * wv.x + (acc.y + bv.y) * wv.y +
              (acc.z + bv.z) * wv.z + (acc.w + bv.w) * wv.w;
    #pragma unroll
    for (int o = 16; o; o >>= 1) s += __shfl_down_sync(0xffffffffu, s, o);
    if (lane == 0) out[wid] = s + fcb[0];
}

// ---------------- launch ----------------
extern "C" void kernel_launch(void* const* d_in, const int* in_sizes, int n_in,
                              void* d_out, int out_size) {
    const float* x   = (const float*)d_in[0];
    const int*   ei  = (const int*)d_in[1];      // int32
    const float* W1  = (const float*)d_in[2];
    const float* a1s = (const float*)d_in[3];
    const float* a1d = (const float*)d_in[4];
    const float* b1  = (const float*)d_in[5];
    const float* W2  = (const float*)d_in[6];
    const float* a2s = (const float*)d_in[7];
    const float* a2d = (const float*)d_in[8];
    const float* b2  = (const float*)d_in[9];
    const float* fcw = (const float*)d_in[10];
    const float* fcb = (const float*)d_in[11];
    float*       out = (float*)d_out;

    const int N = in_sizes[0] / 128;
    const int E = in_sizes[1] / 2;

    float *agg, *h1, *h2pre;
    cudaGetSymbolAddress((void**)&agg,   g_agg);
    cudaGetSymbolAddress((void**)&h1,    g_h1);
    cudaGetSymbolAddress((void**)&h2pre, g_h2pre);

    const int* e_src = ei;
    const int* e_dst = ei + E;

    // CSR by destination (self loops included via cnt init = 1)
    k_init_cnt<<<(N + 255) / 256, 256>>>(N);
    k_hist<<<(E + 255) / 256, 256>>>(e_dst, E);
    k_scan<<<1, 1024>>>(N);
    k_scatter<<<(E + N + 255) / 256, 256>>>(e_src, e_dst, E, N);

    // ---- layer 1 (H=4, C=128): aggregate raw x, then block-diagonal bf16-split GEMM ----
    k_prep_ws<<<1, 512>>>(W1, a1s, a1d);
    k_scores1<<<(N * 32 + 255) / 256, 256>>>(x, N);
    k_passA<4><<<(N * 32 + 255) / 256, 256>>>(N);
    k_aggX<<<(N * 32 + 255) / 256, 256>>>(x, N);
    {
        dim3 grid(1, (N + 127) / 128, 4);   // z = head
        mma_gemm<true><<<grid, 256>>>(N, 128, agg, 512, 128, W1, 512, 128,
                                      h1, 512, 128, b1);
    }

    // ---- layer 2 (H=1, C=128): project then aggregate ----
    {
        dim3 grid(1, (N + 127) / 128, 1);
        mma_gemm<false><<<grid, 256>>>(N, 512, h1, 512, 0, W2, 128, 0,
                                       h2pre, 128, 0, nullptr);
    }
    k_scores2<<<(N * 32 + 255) / 256, 256>>>(h2pre, a2s, a2d, N);
    k_passA<1><<<(N * 32 + 255) / 256, 256>>>(N);
    k_passB2<<<(N * 32 + 255) / 256, 256>>>(b2, fcw, fcb, out, N);
}